// round 6
// baseline (speedup 1.0000x reference)
#include <cuda_runtime.h>
#include <cuda_bf16.h>
#include <math.h>
#include <cstdint>
#include <cstddef>

#define B_   8
#define N_   2048
#define F_   256
#define TM   64
#define TK   32
#define ALPHA 0.2f

// ---------------- device scratch (allocation-free rule) ----------------
__device__ float g_s1[B_ * N_];
__device__ float g_s2[B_ * N_];
__device__ __nv_bfloat16 g_WhT_hi[B_ * F_ * N_];   // [b][f][j]
__device__ __nv_bfloat16 g_WhT_lo[B_ * F_ * N_];

__device__ __forceinline__ uint32_t smem_u32(const void* p) {
    uint32_t a;
    asm("{ .reg .u64 t; cvta.to.shared.u64 t, %1; cvt.u32.u64 %0, t; }"
        : "=r"(a) : "l"(p));
    return a;
}
__device__ __forceinline__ void ldm_x4(uint32_t& r0, uint32_t& r1,
                                       uint32_t& r2, uint32_t& r3, uint32_t addr) {
    asm volatile("ldmatrix.sync.aligned.m8n8.x4.shared.b16 {%0,%1,%2,%3}, [%4];"
                 : "=r"(r0), "=r"(r1), "=r"(r2), "=r"(r3) : "r"(addr));
}
__device__ __forceinline__ void mma_bf16(float* d, const uint32_t* a,
                                         uint32_t b0, uint32_t b1) {
    asm volatile(
        "mma.sync.aligned.m16n8k16.row.col.f32.bf16.bf16.f32 "
        "{%0,%1,%2,%3}, {%4,%5,%6,%7}, {%8,%9}, {%0,%1,%2,%3};"
        : "+f"(d[0]), "+f"(d[1]), "+f"(d[2]), "+f"(d[3])
        : "r"(a[0]), "r"(a[1]), "r"(a[2]), "r"(a[3]), "r"(b0), "r"(b1));
}
__device__ __forceinline__ void cp_async16(uint32_t dst, const void* src) {
    asm volatile("cp.async.cg.shared.global [%0], [%1], 16;"
                 :: "r"(dst), "l"(src) : "memory");
}
#define CP_COMMIT() asm volatile("cp.async.commit_group;" ::: "memory")
#define CP_WAIT0()  asm volatile("cp.async.wait_group 0;" ::: "memory")

// ---------------------------------------------------------------------------
// Kernel 1: Wh = h @ W^T + b ; emits WhT hi/lo (bf16 split, [b][f][j]) + s1/s2
// ---------------------------------------------------------------------------
__global__ void __launch_bounds__(256) k1_gemm(
    const float* __restrict__ h,  const float* __restrict__ Ww,
    const float* __restrict__ Wb, const float* __restrict__ aiw,
    const float* __restrict__ aib, const float* __restrict__ ajw,
    const float* __restrict__ ajb)
{
    __shared__ float hS[TK][TM + 4];
    __shared__ float wS[TK][F_];

    const int t    = threadIdx.x;
    const int row0 = blockIdx.x * TM;
    const int tf   = t & 31;
    const int ti   = t >> 5;
    const int lr   = t >> 2;
    const int lc   = (t & 3) * 8;

    float c[8][8];
#pragma unroll
    for (int i = 0; i < 8; i++)
#pragma unroll
        for (int j = 0; j < 8; j++) c[i][j] = 0.f;

    for (int k0 = 0; k0 < F_; k0 += TK) {
        float4 v0 = *(const float4*)&h[(row0 + lr) * F_ + k0 + lc];
        float4 v1 = *(const float4*)&h[(row0 + lr) * F_ + k0 + lc + 4];
        hS[lc + 0][lr] = v0.x; hS[lc + 1][lr] = v0.y;
        hS[lc + 2][lr] = v0.z; hS[lc + 3][lr] = v0.w;
        hS[lc + 4][lr] = v1.x; hS[lc + 5][lr] = v1.y;
        hS[lc + 6][lr] = v1.z; hS[lc + 7][lr] = v1.w;

#pragma unroll
        for (int q = 0; q < 4; q++) {
            int o = (t >> 2) + q * 64;
            const float* wp = &Ww[o * F_ + k0 + (t & 3) * 8];
            float4 w4 = *(const float4*)wp;
            float4 w5 = *(const float4*)(wp + 4);
            int kk = (t & 3) * 8;
            wS[kk + 0][o] = w4.x; wS[kk + 1][o] = w4.y;
            wS[kk + 2][o] = w4.z; wS[kk + 3][o] = w4.w;
            wS[kk + 4][o] = w5.x; wS[kk + 5][o] = w5.y;
            wS[kk + 6][o] = w5.z; wS[kk + 7][o] = w5.w;
        }
        __syncthreads();

#pragma unroll 4
        for (int kk = 0; kk < TK; kk++) {
            float a[8], bb[8];
            *(float4*)(a)      = *(const float4*)&hS[kk][ti * 8];
            *(float4*)(a + 4)  = *(const float4*)&hS[kk][ti * 8 + 4];
            *(float4*)(bb)     = *(const float4*)&wS[kk][tf * 8];
            *(float4*)(bb + 4) = *(const float4*)&wS[kk][tf * 8 + 4];
#pragma unroll
            for (int i = 0; i < 8; i++)
#pragma unroll
                for (int j = 0; j < 8; j++)
                    c[i][j] = fmaf(a[i], bb[j], c[i][j]);
        }
        __syncthreads();
    }

    float bv[8], av[8], jv[8];
#pragma unroll
    for (int u = 0; u < 8; u++) {
        bv[u] = Wb[tf * 8 + u];
        av[u] = aiw[tf * 8 + u];
        jv[u] = ajw[tf * 8 + u];
    }
    const float aib0 = aib[0], ajb0 = ajb[0];

#pragma unroll
    for (int ii = 0; ii < 8; ii++) {
        int row = row0 + ti * 8 + ii;
        float p1 = 0.f, p2 = 0.f;
#pragma unroll
        for (int u = 0; u < 8; u++) {
            c[ii][u] += bv[u];
            p1 = fmaf(c[ii][u], av[u], p1);
            p2 = fmaf(c[ii][u], jv[u], p2);
        }
#pragma unroll
        for (int off = 16; off > 0; off >>= 1) {
            p1 += __shfl_xor_sync(0xffffffffu, p1, off);
            p2 += __shfl_xor_sync(0xffffffffu, p2, off);
        }
        if (tf == 0) {
            g_s1[row] = p1 + aib0;
            g_s2[row] = p2 + ajb0;
        }
    }

    const int b  = row0 >> 11;
    const int jb = (row0 & (N_ - 1)) + ti * 8;
#pragma unroll
    for (int u = 0; u < 8; u++) {
        int f = tf * 8 + u;
        uint32_t hw[4], lw[4];
#pragma unroll
        for (int e = 0; e < 8; e += 2) {
            float v0 = c[e][u], v1 = c[e + 1][u];
            __nv_bfloat16 h0 = __float2bfloat16(v0), h1 = __float2bfloat16(v1);
            float r0 = v0 - __bfloat162float(h0);
            float r1 = v1 - __bfloat162float(h1);
            __nv_bfloat16 l0 = __float2bfloat16(r0), l1 = __float2bfloat16(r1);
            __nv_bfloat162 hp = __halves2bfloat162(h0, h1);
            __nv_bfloat162 lp = __halves2bfloat162(l0, l1);
            hw[e >> 1] = *(uint32_t*)&hp;
            lw[e >> 1] = *(uint32_t*)&lp;
        }
        size_t dst = ((size_t)(b * F_ + f)) * N_ + jb;
        *(uint4*)(g_WhT_hi + dst) = make_uint4(hw[0], hw[1], hw[2], hw[3]);
        *(uint4*)(g_WhT_lo + dst) = make_uint4(lw[0], lw[1], lw[2], lw[3]);
    }
}

// ---------------------------------------------------------------------------
// Kernel 2: HMMA attention GEMM, 2 CTAs/SM for fill/MMA overlap.
//   CTA: 128 i x 128 f, 256 threads (8 warps, warp tile 32x64).
//   j-chunk 32, double-buffered; B via cp.async (post-barrier issue),
//   adj register-prefetched, s2 staged in smem.
// ---------------------------------------------------------------------------
#define KC2   32
#define NCH2  (N_ / KC2)                   // 64 chunks
#define AST   40
#define BST   40
#define A_BYTES (128 * AST * 2)            // 10240
#define B_BYTES (128 * BST * 2)            // 10240
#define STAGE   (2 * A_BYTES + 2 * B_BYTES)    // 40960
#define DYN_SMEM (2 * STAGE)                   // 81920

__global__ void __launch_bounds__(256, 2) k2_attn(
    const int* __restrict__ adj, float* __restrict__ out)
{
    extern __shared__ __align__(16) char smRaw[];
    __shared__ float s1S[128];
    __shared__ __align__(16) float s2S[N_];    // 8KB, whole batch row of s2
    __shared__ float rsS[128][2];
    __shared__ float rInv[128];

    const int t    = threadIdx.x;
    const int lane = t & 31;
    const int wid  = t >> 5;
    const int wm   = wid & 3;            // i: wm*32
    const int wn   = wid >> 2;           // f: wn*64 (0..1)
    const int b    = blockIdx.x >> 5;
    const int rem  = blockIdx.x & 31;
    const int i0   = (rem >> 1) * 128;
    const int f0   = (rem & 1) * 128;

    const uint32_t smBase = smem_u32(smRaw);

    if (t < 128) s1S[t] = g_s1[b * N_ + i0 + t];
    {
        const float4* s2g = (const float4*)(g_s2 + b * N_);
#pragma unroll
        for (int k = t; k < N_ / 4; k += 256) ((float4*)s2S)[k] = s2g[k];
    }

    // ---- fill roles ----
    const int ig = t >> 1;               // A row 0..127
    const int jg = (t & 1) * 16;         // 16-j half
    const int fB = t >> 1;               // B row 0..127
    const int hB = (t & 1) * 16;

    const int* adjP = adj + (size_t)(b * N_ + i0 + ig) * N_;
    const __nv_bfloat16* bhP = g_WhT_hi + (size_t)(b * F_ + f0 + fB) * N_;
    const __nv_bfloat16* blP = g_WhT_lo + (size_t)(b * F_ + f0 + fB) * N_;

    float acc[2][8][4];
#pragma unroll
    for (int m = 0; m < 2; m++)
#pragma unroll
        for (int n = 0; n < 8; n++)
#pragma unroll
            for (int q = 0; q < 4; q++) acc[m][n][q] = 0.f;
    float lsum = 0.f;

    // ---- prologue: cp.async B(0) into stage 0, adj(0) into regs ----
    {
        uint32_t dH = smBase + 2 * A_BYTES + (uint32_t)(fB * BST + hB) * 2u;
        uint32_t dL = dH + B_BYTES;
        cp_async16(dH,      bhP + hB);
        cp_async16(dH + 16, bhP + hB + 8);
        cp_async16(dL,      blP + hB);
        cp_async16(dL + 16, blP + hB + 8);
        CP_COMMIT();
    }
    int4 pA0 = *(const int4*)(adjP + jg);
    int4 pA1 = *(const int4*)(adjP + jg + 4);
    int4 pA2 = *(const int4*)(adjP + jg + 8);
    int4 pA3 = *(const int4*)(adjP + jg + 12);

    __syncthreads();   // s1S/s2S visible

    for (int c = 0; c < NCH2; ++c) {
        const int      j0 = c * KC2;
        const uint32_t sb = smBase + (c & 1) * STAGE;
        const uint32_t aHiS = sb;
        const uint32_t aLoS = sb + A_BYTES;
        const uint32_t bHiS = sb + 2 * A_BYTES;
        const uint32_t bLoS = bHiS + B_BYTES;

        // ---- A fill: 16 w values (2 blocks of 8) from prefetched adj ----
        const float s1v = s1S[ig];
#pragma unroll
        for (int blk = 0; blk < 2; ++blk) {
            int4 q0 = blk ? pA2 : pA0;
            int4 q1 = blk ? pA3 : pA1;
            const float* s2p = &s2S[j0 + jg + blk * 8];
            float4 u0 = *(const float4*)s2p;
            float4 u1 = *(const float4*)(s2p + 4);
            float xs[8] = {u0.x, u0.y, u0.z, u0.w, u1.x, u1.y, u1.z, u1.w};
            int   av[8] = {q0.x, q0.y, q0.z, q0.w, q1.x, q1.y, q1.z, q1.w};
            uint32_t hw[4], lw[4];
#pragma unroll
            for (int e = 0; e < 8; e += 2) {
                float x0 = s1v + xs[e];     x0 = fmaxf(x0, ALPHA * x0);
                float x1 = s1v + xs[e + 1]; x1 = fmaxf(x1, ALPHA * x1);
                float w0 = (av[e]     > 0) ? __expf(x0) : 0.f;
                float w1 = (av[e + 1] > 0) ? __expf(x1) : 0.f;
                lsum += w0 + w1;
                __nv_bfloat16 h0 = __float2bfloat16(w0), h1 = __float2bfloat16(w1);
                float r0 = w0 - __bfloat162float(h0);
                float r1 = w1 - __bfloat162float(h1);
                __nv_bfloat16 l0 = __float2bfloat16(r0), l1 = __float2bfloat16(r1);
                __nv_bfloat162 hp = __halves2bfloat162(h0, h1);
                __nv_bfloat162 lp = __halves2bfloat162(l0, l1);
                hw[e >> 1] = *(uint32_t*)&hp;
                lw[e >> 1] = *(uint32_t*)&lp;
            }
            uint32_t off = (uint32_t)(ig * AST + jg + blk * 8) * 2u;
            asm volatile("st.shared.v4.b32 [%0], {%1,%2,%3,%4};"
                         :: "r"(aHiS + off), "r"(hw[0]), "r"(hw[1]), "r"(hw[2]), "r"(hw[3]));
            asm volatile("st.shared.v4.b32 [%0], {%1,%2,%3,%4};"
                         :: "r"(aLoS + off), "r"(lw[0]), "r"(lw[1]), "r"(lw[2]), "r"(lw[3]));
        }

        // ---- B(c) must be landed before the barrier ----
        CP_WAIT0();
        __syncthreads();

        // ---- post-barrier: issue B(c+1) cp.async + adj(c+1) prefetch ----
        if (c + 1 < NCH2) {
            const int jn = j0 + KC2;
            uint32_t dH = smBase + ((c + 1) & 1) * STAGE + 2 * A_BYTES
                        + (uint32_t)(fB * BST + hB) * 2u;
            uint32_t dL = dH + B_BYTES;
            cp_async16(dH,      bhP + jn + hB);
            cp_async16(dH + 16, bhP + jn + hB + 8);
            cp_async16(dL,      blP + jn + hB);
            cp_async16(dL + 16, blP + jn + hB + 8);
            CP_COMMIT();
            pA0 = *(const int4*)(adjP + jn + jg);
            pA1 = *(const int4*)(adjP + jn + jg + 4);
            pA2 = *(const int4*)(adjP + jn + jg + 8);
            pA3 = *(const int4*)(adjP + jn + jg + 12);
        }

        // ---- MMA phase ----
#pragma unroll
        for (int ks = 0; ks < 2; ++ks) {
            const int k0 = ks * 16;
            uint32_t ah[2][4], al[2][4];
#pragma unroll
            for (int mt = 0; mt < 2; ++mt) {
                int arow = wm * 32 + mt * 16 + (lane & 15);
                uint32_t aoff = (uint32_t)(arow * AST + k0 + ((lane >> 4) << 3)) * 2u;
                ldm_x4(ah[mt][0], ah[mt][1], ah[mt][2], ah[mt][3], aHiS + aoff);
                ldm_x4(al[mt][0], al[mt][1], al[mt][2], al[mt][3], aLoS + aoff);
            }
#pragma unroll
            for (int pr = 0; pr < 4; ++pr) {
                int n0   = wn * 64 + pr * 16;
                int rowB = n0 + (lane & 7) + ((lane >> 4) << 3);
                int colB = k0 + (((lane >> 3) & 1) << 3);
                uint32_t boff = (uint32_t)(rowB * BST + colB) * 2u;
                uint32_t bh0, bh1, bh2, bh3, bl0, bl1, bl2, bl3;
                ldm_x4(bh0, bh1, bh2, bh3, bHiS + boff);
                ldm_x4(bl0, bl1, bl2, bl3, bLoS + boff);
                mma_bf16(acc[0][pr * 2],     ah[0], bh0, bh1);
                mma_bf16(acc[1][pr * 2],     ah[1], bh0, bh1);
                mma_bf16(acc[0][pr * 2 + 1], ah[0], bh2, bh3);
                mma_bf16(acc[1][pr * 2 + 1], ah[1], bh2, bh3);
                mma_bf16(acc[0][pr * 2],     ah[0], bl0, bl1);
                mma_bf16(acc[1][pr * 2],     ah[1], bl0, bl1);
                mma_bf16(acc[0][pr * 2 + 1], ah[0], bl2, bl3);
                mma_bf16(acc[1][pr * 2 + 1], ah[1], bl2, bl3);
                mma_bf16(acc[0][pr * 2],     al[0], bh0, bh1);
                mma_bf16(acc[1][pr * 2],     al[1], bh0, bh1);
                mma_bf16(acc[0][pr * 2 + 1], al[0], bh2, bh3);
                mma_bf16(acc[1][pr * 2 + 1], al[1], bh2, bh3);
            }
        }
    }

    // ---- row-sum reduce ----
    rsS[ig][t & 1] = lsum;
    __syncthreads();
    if (t < 128) rInv[t] = 1.f / (rsS[t][0] + rsS[t][1]);
    __syncthreads();

    // ---- epilogue: normalize + ELU + store ----
    const int g  = lane >> 2;
    const int tq = lane & 3;
#pragma unroll
    for (int mt = 0; mt < 2; ++mt) {
        int r0l = wm * 32 + mt * 16 + g;
        int r1l = r0l + 8;
        float inv0 = rInv[r0l], inv1 = rInv[r1l];
        size_t o0 = ((size_t)(b * N_ + i0 + r0l)) * F_ + f0;
        size_t o1 = ((size_t)(b * N_ + i0 + r1l)) * F_ + f0;
#pragma unroll
        for (int nt = 0; nt < 8; ++nt) {
            int col = wn * 64 + nt * 8 + 2 * tq;
            float x0 = acc[mt][nt][0] * inv0;
            float x1 = acc[mt][nt][1] * inv0;
            float x2 = acc[mt][nt][2] * inv1;
            float x3 = acc[mt][nt][3] * inv1;
            x0 = (x0 > 0.f) ? x0 : expm1f(x0);
            x1 = (x1 > 0.f) ? x1 : expm1f(x1);
            x2 = (x2 > 0.f) ? x2 : expm1f(x2);
            x3 = (x3 > 0.f) ? x3 : expm1f(x3);
            *(float2*)(out + o0 + col) = make_float2(x0, x1);
            *(float2*)(out + o1 + col) = make_float2(x2, x3);
        }
    }
}

// ---------------------------------------------------------------------------
extern "C" void kernel_launch(void* const* d_in, const int* in_sizes, int n_in,
                              void* d_out, int out_size)
{
    const float* h   = (const float*)d_in[0];
    const int*   adj = (const int*)  d_in[1];
    const float* Ww  = (const float*)d_in[2];
    const float* Wb  = (const float*)d_in[3];
    const float* aiw = (const float*)d_in[4];
    const float* aib = (const float*)d_in[5];
    const float* ajw = (const float*)d_in[6];
    const float* ajb = (const float*)d_in[7];
    float* out = (float*)d_out;

    static bool attrDone = false;
    if (!attrDone) {
        cudaFuncSetAttribute(k2_attn, cudaFuncAttributeMaxDynamicSharedMemorySize,
                             DYN_SMEM);
        attrDone = true;
    }

    k1_gemm<<<(B_ * N_) / TM, 256>>>(h, Ww, Wb, aiw, aib, ajw, ajb);
    k2_attn<<<B_ * 32, 256, DYN_SMEM>>>(adj, out);
}

// round 7
// speedup vs baseline: 1.1409x; 1.1409x over previous
#include <cuda_runtime.h>
#include <cuda_bf16.h>
#include <math.h>
#include <cstdint>
#include <cstddef>

#define B_   8
#define N_   2048
#define F_   256
#define TM   64
#define TK   32
#define ALPHA 0.2f

// ---------------- device scratch (allocation-free rule) ----------------
__device__ float g_s1[B_ * N_];
__device__ float g_s2[B_ * N_];
__device__ __nv_bfloat16 g_WhT_hi[B_ * F_ * N_];   // [b][f][j]
__device__ __nv_bfloat16 g_WhT_lo[B_ * F_ * N_];

__device__ __forceinline__ uint32_t smem_u32(const void* p) {
    uint32_t a;
    asm("{ .reg .u64 t; cvta.to.shared.u64 t, %1; cvt.u32.u64 %0, t; }"
        : "=r"(a) : "l"(p));
    return a;
}
__device__ __forceinline__ void ldm_x4(uint32_t& r0, uint32_t& r1,
                                       uint32_t& r2, uint32_t& r3, uint32_t addr) {
    asm volatile("ldmatrix.sync.aligned.m8n8.x4.shared.b16 {%0,%1,%2,%3}, [%4];"
                 : "=r"(r0), "=r"(r1), "=r"(r2), "=r"(r3) : "r"(addr));
}
__device__ __forceinline__ void mma_bf16(float* d, const uint32_t* a,
                                         uint32_t b0, uint32_t b1) {
    asm volatile(
        "mma.sync.aligned.m16n8k16.row.col.f32.bf16.bf16.f32 "
        "{%0,%1,%2,%3}, {%4,%5,%6,%7}, {%8,%9}, {%0,%1,%2,%3};"
        : "+f"(d[0]), "+f"(d[1]), "+f"(d[2]), "+f"(d[3])
        : "r"(a[0]), "r"(a[1]), "r"(a[2]), "r"(a[3]), "r"(b0), "r"(b1));
}
__device__ __forceinline__ void cp_async16(uint32_t dst, const void* src) {
    asm volatile("cp.async.cg.shared.global [%0], [%1], 16;"
                 :: "r"(dst), "l"(src) : "memory");
}
#define CP_COMMIT() asm volatile("cp.async.commit_group;" ::: "memory")
#define CP_WAIT0()  asm volatile("cp.async.wait_group 0;" ::: "memory")

// w-pair: leaky+exp+mask, bf16 hi/lo split, rowsum accumulate
__device__ __forceinline__ void make_w_pair(float s1v, int a0, int a1,
                                            float s20, float s21,
                                            float& lsum, uint32_t& hiP, uint32_t& loP)
{
    float x0 = s1v + s20; x0 = fmaxf(x0, ALPHA * x0);
    float x1 = s1v + s21; x1 = fmaxf(x1, ALPHA * x1);
    float w0 = (a0 > 0) ? __expf(x0) : 0.f;
    float w1 = (a1 > 0) ? __expf(x1) : 0.f;
    lsum += w0 + w1;
    __nv_bfloat16 h0 = __float2bfloat16(w0), h1 = __float2bfloat16(w1);
    float r0 = w0 - __bfloat162float(h0);
    float r1 = w1 - __bfloat162float(h1);
    __nv_bfloat16 l0 = __float2bfloat16(r0), l1 = __float2bfloat16(r1);
    __nv_bfloat162 hp = __halves2bfloat162(h0, h1);
    __nv_bfloat162 lp = __halves2bfloat162(l0, l1);
    hiP = *(uint32_t*)&hp;
    loP = *(uint32_t*)&lp;
}

// ---------------------------------------------------------------------------
// Kernel 1: Wh = h @ W^T + b ; emits WhT hi/lo (bf16 split, [b][f][j]) + s1/s2
// ---------------------------------------------------------------------------
__global__ void __launch_bounds__(256) k1_gemm(
    const float* __restrict__ h,  const float* __restrict__ Ww,
    const float* __restrict__ Wb, const float* __restrict__ aiw,
    const float* __restrict__ aib, const float* __restrict__ ajw,
    const float* __restrict__ ajb)
{
    __shared__ float hS[TK][TM + 4];
    __shared__ float wS[TK][F_];

    const int t    = threadIdx.x;
    const int row0 = blockIdx.x * TM;
    const int tf   = t & 31;
    const int ti   = t >> 5;
    const int lr   = t >> 2;
    const int lc   = (t & 3) * 8;

    float c[8][8];
#pragma unroll
    for (int i = 0; i < 8; i++)
#pragma unroll
        for (int j = 0; j < 8; j++) c[i][j] = 0.f;

    for (int k0 = 0; k0 < F_; k0 += TK) {
        float4 v0 = *(const float4*)&h[(row0 + lr) * F_ + k0 + lc];
        float4 v1 = *(const float4*)&h[(row0 + lr) * F_ + k0 + lc + 4];
        hS[lc + 0][lr] = v0.x; hS[lc + 1][lr] = v0.y;
        hS[lc + 2][lr] = v0.z; hS[lc + 3][lr] = v0.w;
        hS[lc + 4][lr] = v1.x; hS[lc + 5][lr] = v1.y;
        hS[lc + 6][lr] = v1.z; hS[lc + 7][lr] = v1.w;

#pragma unroll
        for (int q = 0; q < 4; q++) {
            int o = (t >> 2) + q * 64;
            const float* wp = &Ww[o * F_ + k0 + (t & 3) * 8];
            float4 w4 = *(const float4*)wp;
            float4 w5 = *(const float4*)(wp + 4);
            int kk = (t & 3) * 8;
            wS[kk + 0][o] = w4.x; wS[kk + 1][o] = w4.y;
            wS[kk + 2][o] = w4.z; wS[kk + 3][o] = w4.w;
            wS[kk + 4][o] = w5.x; wS[kk + 5][o] = w5.y;
            wS[kk + 6][o] = w5.z; wS[kk + 7][o] = w5.w;
        }
        __syncthreads();

#pragma unroll 4
        for (int kk = 0; kk < TK; kk++) {
            float a[8], bb[8];
            *(float4*)(a)      = *(const float4*)&hS[kk][ti * 8];
            *(float4*)(a + 4)  = *(const float4*)&hS[kk][ti * 8 + 4];
            *(float4*)(bb)     = *(const float4*)&wS[kk][tf * 8];
            *(float4*)(bb + 4) = *(const float4*)&wS[kk][tf * 8 + 4];
#pragma unroll
            for (int i = 0; i < 8; i++)
#pragma unroll
                for (int j = 0; j < 8; j++)
                    c[i][j] = fmaf(a[i], bb[j], c[i][j]);
        }
        __syncthreads();
    }

    float bv[8], av[8], jv[8];
#pragma unroll
    for (int u = 0; u < 8; u++) {
        bv[u] = Wb[tf * 8 + u];
        av[u] = aiw[tf * 8 + u];
        jv[u] = ajw[tf * 8 + u];
    }
    const float aib0 = aib[0], ajb0 = ajb[0];

#pragma unroll
    for (int ii = 0; ii < 8; ii++) {
        int row = row0 + ti * 8 + ii;
        float p1 = 0.f, p2 = 0.f;
#pragma unroll
        for (int u = 0; u < 8; u++) {
            c[ii][u] += bv[u];
            p1 = fmaf(c[ii][u], av[u], p1);
            p2 = fmaf(c[ii][u], jv[u], p2);
        }
#pragma unroll
        for (int off = 16; off > 0; off >>= 1) {
            p1 += __shfl_xor_sync(0xffffffffu, p1, off);
            p2 += __shfl_xor_sync(0xffffffffu, p2, off);
        }
        if (tf == 0) {
            g_s1[row] = p1 + aib0;
            g_s2[row] = p2 + ajb0;
        }
    }

    const int b  = row0 >> 11;
    const int jb = (row0 & (N_ - 1)) + ti * 8;
#pragma unroll
    for (int u = 0; u < 8; u++) {
        int f = tf * 8 + u;
        uint32_t hw[4], lw[4];
#pragma unroll
        for (int e = 0; e < 8; e += 2) {
            float v0 = c[e][u], v1 = c[e + 1][u];
            __nv_bfloat16 h0 = __float2bfloat16(v0), h1 = __float2bfloat16(v1);
            float r0 = v0 - __bfloat162float(h0);
            float r1 = v1 - __bfloat162float(h1);
            __nv_bfloat16 l0 = __float2bfloat16(r0), l1 = __float2bfloat16(r1);
            __nv_bfloat162 hp = __halves2bfloat162(h0, h1);
            __nv_bfloat162 lp = __halves2bfloat162(l0, l1);
            hw[e >> 1] = *(uint32_t*)&hp;
            lw[e >> 1] = *(uint32_t*)&lp;
        }
        size_t dst = ((size_t)(b * F_ + f)) * N_ + jb;
        *(uint4*)(g_WhT_hi + dst) = make_uint4(hw[0], hw[1], hw[2], hw[3]);
        *(uint4*)(g_WhT_lo + dst) = make_uint4(lw[0], lw[1], lw[2], lw[3]);
    }
}

// ---------------------------------------------------------------------------
// Kernel 2: HMMA attention GEMM. CTA 128i x 256f, 512 thr, 1 sync/chunk.
//   Next chunk's exp/split compute is source-interleaved into the MMA block,
//   B arrives via cp.async issued at segment start, A stored at segment end.
// ---------------------------------------------------------------------------
#define KC2   32
#define NCH2  (N_ / KC2)                  // 64 chunks
#define AST   40
#define BST   40
#define A_BYTES (128 * AST * 2)           // 10240
#define B_BYTES (256 * BST * 2)           // 20480
#define STAGE   (2 * A_BYTES + 2 * B_BYTES)   // 61440
#define DYN_SMEM (2 * STAGE)                  // 122880

__global__ void __launch_bounds__(512, 1) k2_attn(
    const int* __restrict__ adj, float* __restrict__ out)
{
    extern __shared__ __align__(16) char smRaw[];
    __shared__ float s1S[128];
    __shared__ __align__(16) float s2S[N_];   // 8KB: whole batch s2 row
    __shared__ float rsS[128][4];
    __shared__ float rInv[128];

    const int t    = threadIdx.x;
    const int lane = t & 31;
    const int wid  = t >> 5;
    const int wm   = wid & 3;
    const int wn   = wid >> 2;
    const int b    = blockIdx.x >> 4;
    const int i0   = (blockIdx.x & 15) * 128;

    const uint32_t smBase = smem_u32(smRaw);

    if (t < 128) s1S[t] = g_s1[b * N_ + i0 + t];
    {
        const float4* s2g = (const float4*)(g_s2 + b * N_);
#pragma unroll
        for (int k = t; k < N_ / 4; k += 512) ((float4*)s2S)[k] = s2g[k];
    }

    // ---- roles ----
    const int ig = t >> 2;                   // A row 0..127
    const int jg = (t & 3) * 8;              // 8-j subgroup
    const int fB = t >> 1;                   // B row 0..255
    const int hB = (t & 1) * 16;

    const int* adjP = adj + (size_t)(b * N_ + i0 + ig) * N_;
    const __nv_bfloat16* bhP = g_WhT_hi + (size_t)(b * F_ + fB) * N_;
    const __nv_bfloat16* blP = g_WhT_lo + (size_t)(b * F_ + fB) * N_;

    float acc[2][8][4];
#pragma unroll
    for (int m = 0; m < 2; m++)
#pragma unroll
        for (int n = 0; n < 8; n++)
#pragma unroll
            for (int q = 0; q < 4; q++) acc[m][n][q] = 0.f;
    float lsum = 0.f;

    uint32_t hw[4], lw[4];      // w-pairs for the upcoming chunk

    __syncthreads();            // s1S/s2S visible

    // ---- prologue: wreg(0), B(0), A(0) ----
    {
        int4 a0 = *(const int4*)(adjP + jg);
        int4 a1 = *(const int4*)(adjP + jg + 4);
        const float s1v = s1S[ig];
        make_w_pair(s1v, a0.x, a0.y, s2S[jg + 0], s2S[jg + 1], lsum, hw[0], lw[0]);
        make_w_pair(s1v, a0.z, a0.w, s2S[jg + 2], s2S[jg + 3], lsum, hw[1], lw[1]);
        make_w_pair(s1v, a1.x, a1.y, s2S[jg + 4], s2S[jg + 5], lsum, hw[2], lw[2]);
        make_w_pair(s1v, a1.z, a1.w, s2S[jg + 6], s2S[jg + 7], lsum, hw[3], lw[3]);

        uint32_t dH = smBase + 2 * A_BYTES + (uint32_t)(fB * BST + hB) * 2u;
        cp_async16(dH,      bhP + hB);
        cp_async16(dH + 16, bhP + hB + 8);
        cp_async16(dH + B_BYTES,      blP + hB);
        cp_async16(dH + B_BYTES + 16, blP + hB + 8);
        CP_COMMIT();

        uint32_t off = (uint32_t)(ig * AST + jg) * 2u;
        asm volatile("st.shared.v4.b32 [%0], {%1,%2,%3,%4};"
                     :: "r"(smBase + off), "r"(hw[0]), "r"(hw[1]), "r"(hw[2]), "r"(hw[3]));
        asm volatile("st.shared.v4.b32 [%0], {%1,%2,%3,%4};"
                     :: "r"(smBase + A_BYTES + off), "r"(lw[0]), "r"(lw[1]), "r"(lw[2]), "r"(lw[3]));
        CP_WAIT0();
    }
    __syncthreads();

    for (int c = 0; c < NCH2; ++c) {
        const uint32_t sb   = smBase + (c & 1) * STAGE;
        const uint32_t sbN  = smBase + ((c + 1) & 1) * STAGE;
        const uint32_t aHiS = sb;
        const uint32_t aLoS = sb + A_BYTES;
        const uint32_t bHiS = sb + 2 * A_BYTES;
        const uint32_t bLoS = bHiS + B_BYTES;
        const bool doNext = (c + 1 < NCH2);
        const int  jn = (c + 1) * KC2;

        // ---- segment start: launch B(c+1) + adj(c+1) loads (fly under MMAs) ----
        int4 pA0, pA1;
        if (doNext) {
            uint32_t dH = sbN + 2 * A_BYTES + (uint32_t)(fB * BST + hB) * 2u;
            cp_async16(dH,      bhP + jn + hB);
            cp_async16(dH + 16, bhP + jn + hB + 8);
            cp_async16(dH + B_BYTES,      blP + jn + hB);
            cp_async16(dH + B_BYTES + 16, blP + jn + hB + 8);
            CP_COMMIT();
            pA0 = *(const int4*)(adjP + jn + jg);
            pA1 = *(const int4*)(adjP + jn + jg + 4);
        }
        const float s1v = s1S[ig];

        // ---- MMA(c), with wreg(c+1) computes interleaved in the same block ----
#pragma unroll
        for (int ks = 0; ks < 2; ++ks) {
            const int k0 = ks * 16;
            uint32_t ah[2][4], al[2][4];
#pragma unroll
            for (int mt = 0; mt < 2; ++mt) {
                int arow = wm * 32 + mt * 16 + (lane & 15);
                uint32_t aoff = (uint32_t)(arow * AST + k0 + ((lane >> 4) << 3)) * 2u;
                ldm_x4(ah[mt][0], ah[mt][1], ah[mt][2], ah[mt][3], aHiS + aoff);
                ldm_x4(al[mt][0], al[mt][1], al[mt][2], al[mt][3], aLoS + aoff);
            }
#pragma unroll
            for (int pr = 0; pr < 4; ++pr) {
                int n0   = wn * 64 + pr * 16;
                int rowB = n0 + (lane & 7) + ((lane >> 4) << 3);
                int colB = k0 + (((lane >> 3) & 1) << 3);
                uint32_t boff = (uint32_t)(rowB * BST + colB) * 2u;
                uint32_t bh0, bh1, bh2, bh3, bl0, bl1, bl2, bl3;
                ldm_x4(bh0, bh1, bh2, bh3, bHiS + boff);
                ldm_x4(bl0, bl1, bl2, bl3, bLoS + boff);
                mma_bf16(acc[0][pr * 2],     ah[0], bh0, bh1);
                mma_bf16(acc[1][pr * 2],     ah[1], bh0, bh1);
                mma_bf16(acc[0][pr * 2 + 1], ah[0], bh2, bh3);
                mma_bf16(acc[1][pr * 2 + 1], ah[1], bh2, bh3);
                mma_bf16(acc[0][pr * 2],     ah[0], bl0, bl1);
                mma_bf16(acc[1][pr * 2],     ah[1], bl0, bl1);
                mma_bf16(acc[0][pr * 2 + 1], ah[0], bl2, bl3);
                mma_bf16(acc[1][pr * 2 + 1], ah[1], bl2, bl3);
                mma_bf16(acc[0][pr * 2],     al[0], bh0, bh1);
                mma_bf16(acc[1][pr * 2],     al[1], bh0, bh1);
                mma_bf16(acc[0][pr * 2 + 1], al[0], bh2, bh3);
                mma_bf16(acc[1][pr * 2 + 1], al[1], bh2, bh3);

                // interleaved next-chunk w computes (independent of MMAs;
                // ptxas schedules MUFU/CVT into tensor-pipe gaps)
                if (doNext && ks == 1) {
                    int a0 = (pr < 2) ? ((pr == 0) ? pA0.x : pA0.z)
                                      : ((pr == 2) ? pA1.x : pA1.z);
                    int a1 = (pr < 2) ? ((pr == 0) ? pA0.y : pA0.w)
                                      : ((pr == 2) ? pA1.y : pA1.w);
                    make_w_pair(s1v, a0, a1,
                                s2S[jn + jg + 2 * pr], s2S[jn + jg + 2 * pr + 1],
                                lsum, hw[pr], lw[pr]);
                }
            }
        }

        // ---- segment end: store A(c+1), drain B(c+1) ----
        if (doNext) {
            uint32_t off = (uint32_t)(ig * AST + jg) * 2u;
            asm volatile("st.shared.v4.b32 [%0], {%1,%2,%3,%4};"
                         :: "r"(sbN + off), "r"(hw[0]), "r"(hw[1]), "r"(hw[2]), "r"(hw[3]));
            asm volatile("st.shared.v4.b32 [%0], {%1,%2,%3,%4};"
                         :: "r"(sbN + A_BYTES + off), "r"(lw[0]), "r"(lw[1]), "r"(lw[2]), "r"(lw[3]));
            CP_WAIT0();
        }
        __syncthreads();
    }

    // ---- row-sum reduce ----
    rsS[ig][t & 3] = lsum;
    __syncthreads();
    if (t < 128) rInv[t] = 1.f / (rsS[t][0] + rsS[t][1] + rsS[t][2] + rsS[t][3]);
    __syncthreads();

    // ---- epilogue: normalize + ELU + store ----
    const int g  = lane >> 2;
    const int tq = lane & 3;
#pragma unroll
    for (int mt = 0; mt < 2; ++mt) {
        int r0l = wm * 32 + mt * 16 + g;
        int r1l = r0l + 8;
        float inv0 = rInv[r0l], inv1 = rInv[r1l];
        size_t o0 = ((size_t)(b * N_ + i0 + r0l)) * F_;
        size_t o1 = ((size_t)(b * N_ + i0 + r1l)) * F_;
#pragma unroll
        for (int nt = 0; nt < 8; ++nt) {
            int col = wn * 64 + nt * 8 + 2 * tq;
            float x0 = acc[mt][nt][0] * inv0;
            float x1 = acc[mt][nt][1] * inv0;
            float x2 = acc[mt][nt][2] * inv1;
            float x3 = acc[mt][nt][3] * inv1;
            x0 = (x0 > 0.f) ? x0 : expm1f(x0);
            x1 = (x1 > 0.f) ? x1 : expm1f(x1);
            x2 = (x2 > 0.f) ? x2 : expm1f(x2);
            x3 = (x3 > 0.f) ? x3 : expm1f(x3);
            *(float2*)(out + o0 + col) = make_float2(x0, x1);
            *(float2*)(out + o1 + col) = make_float2(x2, x3);
        }
    }
}

// ---------------------------------------------------------------------------
extern "C" void kernel_launch(void* const* d_in, const int* in_sizes, int n_in,
                              void* d_out, int out_size)
{
    const float* h   = (const float*)d_in[0];
    const int*   adj = (const int*)  d_in[1];
    const float* Ww  = (const float*)d_in[2];
    const float* Wb  = (const float*)d_in[3];
    const float* aiw = (const float*)d_in[4];
    const float* aib = (const float*)d_in[5];
    const float* ajw = (const float*)d_in[6];
    const float* ajb = (const float*)d_in[7];
    float* out = (float*)d_out;

    static bool attrDone = false;
    if (!attrDone) {
        cudaFuncSetAttribute(k2_attn, cudaFuncAttributeMaxDynamicSharedMemorySize,
                             DYN_SMEM);
        attrDone = true;
    }

    k1_gemm<<<(B_ * N_) / TM, 256>>>(h, Ww, Wb, aiw, aib, ajw, ajb);
    k2_attn<<<B_ * (N_ / 128), 512, DYN_SMEM>>>(adj, out);
}